// round 1
// baseline (speedup 1.0000x reference)
#include <cuda_runtime.h>

#define NN 200000
#define NE 6400000
#define FIN 128
#define HID 16

// Scratch (device globals — no allocation allowed)
__device__ float g_h[NN * HID];    // layer input features (h1pre, then h2pre)
__device__ float g_agg[NN * HID];  // scatter-add accumulator (reused both layers)

// ---------------------------------------------------------------------------
// Zero the aggregation buffer (float4 stores)
// ---------------------------------------------------------------------------
__global__ void zero_kernel(float* __restrict__ p, int n4) {
    int i = blockIdx.x * blockDim.x + threadIdx.x;
    if (i < n4) ((float4*)p)[i] = make_float4(0.f, 0.f, 0.f, 0.f);
}

// ---------------------------------------------------------------------------
// h1pre = x @ W1   (N x 128 @ 128 x 16), warp per node.
// sWt[j*FIN + k] = W1[k][j]  -> lane l loads float4 {W[4l..4l+3][j]} : LDS.128,
// conflict-free (consecutive 16B per lane).
// ---------------------------------------------------------------------------
__global__ void gemm1_kernel(const float* __restrict__ x,
                             const float* __restrict__ W1,
                             float* __restrict__ out) {
    __shared__ float sWt[HID * FIN];
    for (int i = threadIdx.x; i < HID * FIN; i += blockDim.x) {
        int j = i / FIN, k = i % FIN;
        sWt[i] = W1[k * HID + j];
    }
    __syncthreads();

    int gwarp = (blockIdx.x * blockDim.x + threadIdx.x) >> 5;
    int lane  = threadIdx.x & 31;
    if (gwarp >= NN) return;

    float4 xv = ((const float4*)(x + (size_t)gwarp * FIN))[lane];

    float acc[HID];
    const float4* sWt4 = (const float4*)sWt;
#pragma unroll
    for (int j = 0; j < HID; j++) {
        float4 wv = sWt4[j * (FIN / 4) + lane];
        acc[j] = xv.x * wv.x + xv.y * wv.y + xv.z * wv.z + xv.w * wv.w;
    }
#pragma unroll
    for (int j = 0; j < HID; j++) {
#pragma unroll
        for (int off = 16; off; off >>= 1)
            acc[j] += __shfl_xor_sync(0xFFFFFFFFu, acc[j], off);
    }
    if (lane < HID) out[(size_t)gwarp * HID + lane] = acc[lane];
}

// ---------------------------------------------------------------------------
// Edge scatter: agg[dst] += w * h[src]   (one thread per edge, 4x red.v4.f32)
// ---------------------------------------------------------------------------
__global__ void scatter_kernel(const int* __restrict__ src,
                               const int* __restrict__ dst,
                               const float* __restrict__ w,
                               const float* __restrict__ h,
                               float* __restrict__ agg) {
    int e = blockIdx.x * blockDim.x + threadIdx.x;
    if (e >= NE) return;
    int s = __ldg(src + e);
    int d = __ldg(dst + e);
    float we = __ldg(w + e);

    const float4* hs = (const float4*)(h + (size_t)s * HID);
    float* ad = agg + (size_t)d * HID;
#pragma unroll
    for (int i = 0; i < 4; i++) {
        float4 v = __ldg(hs + i);
        v.x *= we; v.y *= we; v.z *= we; v.w *= we;
        asm volatile(
            "red.global.add.v4.f32 [%0], {%1, %2, %3, %4};"
            :: "l"(ad + i * 4), "f"(v.x), "f"(v.y), "f"(v.z), "f"(v.w)
            : "memory");
    }
}

// ---------------------------------------------------------------------------
// h2pre = relu(agg + b1) @ W2    (thread per node, W2 16x16 in shared)
// ---------------------------------------------------------------------------
__global__ void mid_kernel(const float* __restrict__ agg,
                           const float* __restrict__ b1,
                           const float* __restrict__ W2,
                           float* __restrict__ out) {
    __shared__ float sW[HID * HID];
    __shared__ float sb[HID];
    for (int i = threadIdx.x; i < HID * HID; i += blockDim.x) sW[i] = W2[i];
    if (threadIdx.x < HID) sb[threadIdx.x] = b1[threadIdx.x];
    __syncthreads();

    int n = blockIdx.x * blockDim.x + threadIdx.x;
    if (n >= NN) return;

    float a[HID];
    const float4* ap = (const float4*)(agg + (size_t)n * HID);
#pragma unroll
    for (int i = 0; i < 4; i++) {
        float4 v = ap[i];
        a[4 * i + 0] = v.x; a[4 * i + 1] = v.y;
        a[4 * i + 2] = v.z; a[4 * i + 3] = v.w;
    }
#pragma unroll
    for (int k = 0; k < HID; k++) a[k] = fmaxf(a[k] + sb[k], 0.f);

    float o[HID];
#pragma unroll
    for (int j = 0; j < HID; j++) {
        float acc = 0.f;
#pragma unroll
        for (int k = 0; k < HID; k++) acc += a[k] * sW[k * HID + j];
        o[j] = acc;
    }
    float4* op = (float4*)(out + (size_t)n * HID);
#pragma unroll
    for (int i = 0; i < 4; i++)
        op[i] = make_float4(o[4 * i], o[4 * i + 1], o[4 * i + 2], o[4 * i + 3]);
}

// ---------------------------------------------------------------------------
// out = relu(agg + b2) @ Wd + bd   (thread per node -> scalar)
// ---------------------------------------------------------------------------
__global__ void final_kernel(const float* __restrict__ agg,
                             const float* __restrict__ b2,
                             const float* __restrict__ Wd,
                             const float* __restrict__ bd,
                             float* __restrict__ out) {
    __shared__ float sb[HID], sw[HID], sbd;
    if (threadIdx.x < HID) { sb[threadIdx.x] = b2[threadIdx.x]; sw[threadIdx.x] = Wd[threadIdx.x]; }
    if (threadIdx.x == 0) sbd = bd[0];
    __syncthreads();

    int n = blockIdx.x * blockDim.x + threadIdx.x;
    if (n >= NN) return;

    const float4* ap = (const float4*)(agg + (size_t)n * HID);
    float acc = sbd;
#pragma unroll
    for (int i = 0; i < 4; i++) {
        float4 v = ap[i];
        acc += fmaxf(v.x + sb[4 * i + 0], 0.f) * sw[4 * i + 0];
        acc += fmaxf(v.y + sb[4 * i + 1], 0.f) * sw[4 * i + 1];
        acc += fmaxf(v.z + sb[4 * i + 2], 0.f) * sw[4 * i + 2];
        acc += fmaxf(v.w + sb[4 * i + 3], 0.f) * sw[4 * i + 3];
    }
    out[n] = acc;
}

// ---------------------------------------------------------------------------
extern "C" void kernel_launch(void* const* d_in, const int* in_sizes, int n_in,
                              void* d_out, int out_size) {
    const float* x   = (const float*)d_in[0];
    const int*   src = (const int*)d_in[1];
    const int*   dst = (const int*)d_in[2];
    const float* ew  = (const float*)d_in[3];
    const float* W1  = (const float*)d_in[4];
    const float* b1  = (const float*)d_in[5];
    const float* W2  = (const float*)d_in[6];
    const float* b2  = (const float*)d_in[7];
    const float* Wd  = (const float*)d_in[8];
    const float* bd  = (const float*)d_in[9];
    float* out = (float*)d_out;

    float *g_h_p, *g_agg_p;
    cudaGetSymbolAddress((void**)&g_h_p, g_h);
    cudaGetSymbolAddress((void**)&g_agg_p, g_agg);

    const int TPB = 256;
    const int n4 = NN * HID / 4;                 // 800000
    const int zero_blocks = (n4 + TPB - 1) / TPB;
    const int gemm1_blocks = (NN * 32 + TPB - 1) / TPB;   // warp per node
    const int scat_blocks = (NE + TPB - 1) / TPB;
    const int node_blocks = (NN + TPB - 1) / TPB;

    // Layer 1
    zero_kernel<<<zero_blocks, TPB>>>(g_agg_p, n4);
    gemm1_kernel<<<gemm1_blocks, TPB>>>(x, W1, g_h_p);
    scatter_kernel<<<scat_blocks, TPB>>>(src, dst, ew, g_h_p, g_agg_p);
    // relu(agg+b1) @ W2 -> g_h (reuse)
    mid_kernel<<<node_blocks, TPB>>>(g_agg_p, b1, W2, g_h_p);
    // Layer 2
    zero_kernel<<<zero_blocks, TPB>>>(g_agg_p, n4);
    scatter_kernel<<<scat_blocks, TPB>>>(src, dst, ew, g_h_p, g_agg_p);
    // Final dense
    final_kernel<<<node_blocks, TPB>>>(g_agg_p, b2, Wd, bd, out);
}

// round 2
// speedup vs baseline: 1.3298x; 1.3298x over previous
#include <cuda_runtime.h>

#define NN 200000
#define NE 6400000
#define FIN 128
#define HID 16

// Scratch (device globals — no allocation allowed)
__device__ float g_h[NN * HID];    // layer input features (h1pre, then h2pre)
__device__ float g_agg[NN * HID];  // scatter-add accumulator (reused both layers)

// ---------------------------------------------------------------------------
// Zero the aggregation buffer (float4 stores)
// ---------------------------------------------------------------------------
__global__ void zero_kernel(float* __restrict__ p, int n4) {
    int i = blockIdx.x * blockDim.x + threadIdx.x;
    if (i < n4) ((float4*)p)[i] = make_float4(0.f, 0.f, 0.f, 0.f);
}

// ---------------------------------------------------------------------------
// h1pre = x @ W1   (N x 128 @ 128 x 16), warp per node.
// ---------------------------------------------------------------------------
__global__ void gemm1_kernel(const float* __restrict__ x,
                             const float* __restrict__ W1,
                             float* __restrict__ out) {
    __shared__ float sWt[HID * FIN];
    for (int i = threadIdx.x; i < HID * FIN; i += blockDim.x) {
        int j = i / FIN, k = i % FIN;
        sWt[i] = W1[k * HID + j];
    }
    __syncthreads();

    int gwarp = (blockIdx.x * blockDim.x + threadIdx.x) >> 5;
    int lane  = threadIdx.x & 31;
    if (gwarp >= NN) return;

    float4 xv = ((const float4*)(x + (size_t)gwarp * FIN))[lane];

    float acc[HID];
    const float4* sWt4 = (const float4*)sWt;
#pragma unroll
    for (int j = 0; j < HID; j++) {
        float4 wv = sWt4[j * (FIN / 4) + lane];
        acc[j] = xv.x * wv.x + xv.y * wv.y + xv.z * wv.z + xv.w * wv.w;
    }
#pragma unroll
    for (int j = 0; j < HID; j++) {
#pragma unroll
        for (int off = 16; off; off >>= 1)
            acc[j] += __shfl_xor_sync(0xFFFFFFFFu, acc[j], off);
    }
    if (lane < HID) out[(size_t)gwarp * HID + lane] = acc[lane];
}

// ---------------------------------------------------------------------------
// Edge scatter: agg[dst] += w * h[src]
// 4 lanes per edge: lanes 4e..4e+3 handle edge e's four float4 chunks.
// Each warp instruction touches 8 edges x 64B contiguous -> 16 sectors
// (the minimum), halving L1tex wavefront traffic vs 1-thread-per-edge.
// ---------------------------------------------------------------------------
__global__ void scatter4_kernel(const int* __restrict__ src,
                                const int* __restrict__ dst,
                                const float* __restrict__ w,
                                const float* __restrict__ h,
                                float* __restrict__ agg) {
    long long t = (long long)blockIdx.x * blockDim.x + threadIdx.x;
    int e = (int)(t >> 2);
    int j = (int)(t & 3);
    if (e >= NE) return;

    int   s  = __ldg(src + e);   // 4-lane broadcast within warp
    int   d  = __ldg(dst + e);
    float we = __ldg(w + e);

    float4 v = __ldg((const float4*)(h + (size_t)s * HID) + j);
    v.x *= we; v.y *= we; v.z *= we; v.w *= we;

    float* ad = agg + (size_t)d * HID + 4 * j;
    asm volatile(
        "red.global.add.v4.f32 [%0], {%1, %2, %3, %4};"
        :: "l"(ad), "f"(v.x), "f"(v.y), "f"(v.z), "f"(v.w)
        : "memory");
}

// ---------------------------------------------------------------------------
// h2pre = relu(agg + b1) @ W2 ; also RESETS agg to zero for layer 2
// ---------------------------------------------------------------------------
__global__ void mid_kernel(float* __restrict__ agg,
                           const float* __restrict__ b1,
                           const float* __restrict__ W2,
                           float* __restrict__ out) {
    __shared__ float sW[HID * HID];
    __shared__ float sb[HID];
    for (int i = threadIdx.x; i < HID * HID; i += blockDim.x) sW[i] = W2[i];
    if (threadIdx.x < HID) sb[threadIdx.x] = b1[threadIdx.x];
    __syncthreads();

    int n = blockIdx.x * blockDim.x + threadIdx.x;
    if (n >= NN) return;

    float a[HID];
    float4* ap = (float4*)(agg + (size_t)n * HID);
#pragma unroll
    for (int i = 0; i < 4; i++) {
        float4 v = ap[i];
        a[4 * i + 0] = v.x; a[4 * i + 1] = v.y;
        a[4 * i + 2] = v.z; a[4 * i + 3] = v.w;
    }
    // reset for the next scatter pass (fused zero)
#pragma unroll
    for (int i = 0; i < 4; i++) ap[i] = make_float4(0.f, 0.f, 0.f, 0.f);

#pragma unroll
    for (int k = 0; k < HID; k++) a[k] = fmaxf(a[k] + sb[k], 0.f);

    float o[HID];
#pragma unroll
    for (int j = 0; j < HID; j++) {
        float acc = 0.f;
#pragma unroll
        for (int k = 0; k < HID; k++) acc += a[k] * sW[k * HID + j];
        o[j] = acc;
    }
    float4* op = (float4*)(out + (size_t)n * HID);
#pragma unroll
    for (int i = 0; i < 4; i++)
        op[i] = make_float4(o[4 * i], o[4 * i + 1], o[4 * i + 2], o[4 * i + 3]);
}

// ---------------------------------------------------------------------------
// out = relu(agg + b2) @ Wd + bd   (thread per node -> scalar)
// ---------------------------------------------------------------------------
__global__ void final_kernel(const float* __restrict__ agg,
                             const float* __restrict__ b2,
                             const float* __restrict__ Wd,
                             const float* __restrict__ bd,
                             float* __restrict__ out) {
    __shared__ float sb[HID], sw[HID], sbd;
    if (threadIdx.x < HID) { sb[threadIdx.x] = b2[threadIdx.x]; sw[threadIdx.x] = Wd[threadIdx.x]; }
    if (threadIdx.x == 0) sbd = bd[0];
    __syncthreads();

    int n = blockIdx.x * blockDim.x + threadIdx.x;
    if (n >= NN) return;

    const float4* ap = (const float4*)(agg + (size_t)n * HID);
    float acc = sbd;
#pragma unroll
    for (int i = 0; i < 4; i++) {
        float4 v = ap[i];
        acc += fmaxf(v.x + sb[4 * i + 0], 0.f) * sw[4 * i + 0];
        acc += fmaxf(v.y + sb[4 * i + 1], 0.f) * sw[4 * i + 1];
        acc += fmaxf(v.z + sb[4 * i + 2], 0.f) * sw[4 * i + 2];
        acc += fmaxf(v.w + sb[4 * i + 3], 0.f) * sw[4 * i + 3];
    }
    out[n] = acc;
}

// ---------------------------------------------------------------------------
extern "C" void kernel_launch(void* const* d_in, const int* in_sizes, int n_in,
                              void* d_out, int out_size) {
    const float* x   = (const float*)d_in[0];
    const int*   src = (const int*)d_in[1];
    const int*   dst = (const int*)d_in[2];
    const float* ew  = (const float*)d_in[3];
    const float* W1  = (const float*)d_in[4];
    const float* b1  = (const float*)d_in[5];
    const float* W2  = (const float*)d_in[6];
    const float* b2  = (const float*)d_in[7];
    const float* Wd  = (const float*)d_in[8];
    const float* bd  = (const float*)d_in[9];
    float* out = (float*)d_out;

    float *g_h_p, *g_agg_p;
    cudaGetSymbolAddress((void**)&g_h_p, g_h);
    cudaGetSymbolAddress((void**)&g_agg_p, g_agg);

    const int TPB = 256;
    const int n4 = NN * HID / 4;                          // 800000
    const int zero_blocks  = (n4 + TPB - 1) / TPB;
    const int gemm1_blocks = (NN * 32 + TPB - 1) / TPB;   // warp per node
    const long long scat_threads = (long long)NE * 4;     // 4 lanes per edge
    const int scat_blocks  = (int)((scat_threads + TPB - 1) / TPB);
    const int node_blocks  = (NN + TPB - 1) / TPB;

    // Layer 1
    zero_kernel<<<zero_blocks, TPB>>>(g_agg_p, n4);
    gemm1_kernel<<<gemm1_blocks, TPB>>>(x, W1, g_h_p);
    scatter4_kernel<<<scat_blocks, TPB>>>(src, dst, ew, g_h_p, g_agg_p);
    // relu(agg+b1) @ W2 -> g_h, and zero agg for layer 2
    mid_kernel<<<node_blocks, TPB>>>(g_agg_p, b1, W2, g_h_p);
    // Layer 2
    scatter4_kernel<<<scat_blocks, TPB>>>(src, dst, ew, g_h_p, g_agg_p);
    // Final dense
    final_kernel<<<node_blocks, TPB>>>(g_agg_p, b2, Wd, bd, out);
}